// round 5
// baseline (speedup 1.0000x reference)
#include <cuda_runtime.h>
#include <cuda_bf16.h>
#include <cstdint>

// Problem constants (match reference setup_inputs)
#define T_TABLES 8
#define N_ROWS   100000
#define EMB_D    128
#define N_BAGS_B 8192

#define CTAS_PER_SM 6
#define NUM_SMS     148
#define CTAS        (NUM_SMS * CTAS_PER_SM)   // 888
#define THREADS     256                       // 8 warps per CTA

// Persistent kernel: each warp grid-strides over bags.
// Lane l owns floats [4l, 4l+4) of the D=128 row.
__global__ __launch_bounds__(THREADS, CTAS_PER_SM) void emb_bag_kernel(
    const int* __restrict__ indices,
    const int* __restrict__ offsets,
    const float* __restrict__ weights,
    float* __restrict__ out)
{
    const int lane        = threadIdx.x & 31;
    const int warp0       = (blockIdx.x * THREADS + threadIdx.x) >> 5;
    const int total_warps = (CTAS * THREADS) >> 5;
    const int num_bags    = T_TABLES * N_BAGS_B;

    const char* __restrict__ wbytes =
        (const char*)weights + (unsigned)lane * 16u;

    int bag = warp0;
    if (bag >= num_bags) return;

    // Prefetch state for the first bag handled by this warp.
    int pf_start = offsets[bag];
    int pf_end   = offsets[bag + 1];
    int pf_idx   = (lane < pf_end - pf_start) ? indices[pf_start + lane] : 0;

    while (bag < num_bags) {
        const int t     = bag / N_BAGS_B;
        const int b     = bag - t * N_BAGS_B;
        const int start = pf_start;
        const int end   = pf_end;
        int       myidx = pf_idx;

        // Issue next bag's index/offset loads early so their latency hides
        // under this bag's gather burst.
        const int next_bag = bag + total_warps;
        if (next_bag < num_bags) {
            pf_start = offsets[next_bag];
            pf_end   = offsets[next_bag + 1];
            pf_idx   = (lane < pf_end - pf_start) ? indices[pf_start + lane] : 0;
        }

        // Table base: 64-bit once per bag; per-row offset is 32-bit (<51.2MB).
        const char* __restrict__ wbase =
            wbytes + (long long)t * (N_ROWS * EMB_D * 4ll);

        float4 acc = make_float4(0.f, 0.f, 0.f, 0.f);

        const int n0 = end - start;
        if (n0 == 32) {
            #pragma unroll
            for (int j = 0; j < 32; ++j) {
                const unsigned r = (unsigned)__shfl_sync(0xffffffffu, myidx, j);
                const float4 v = __ldg((const float4*)(wbase + (r << 9)));
                acc.x += v.x; acc.y += v.y; acc.z += v.z; acc.w += v.w;
            }
        } else {
            // Generic path: bags longer/shorter than 32.
            int i = start;
            int cur = myidx;
            int n = min(32, end - i);
            while (n > 0) {
                for (int j = 0; j < n; ++j) {
                    const unsigned r = (unsigned)__shfl_sync(0xffffffffu, cur, j);
                    const float4 v = __ldg((const float4*)(wbase + (r << 9)));
                    acc.x += v.x; acc.y += v.y; acc.z += v.z; acc.w += v.w;
                }
                i += n;
                n = min(32, end - i);
                if (n > 0) cur = (lane < n) ? indices[i + lane] : 0;
            }
        }

        // Output layout: [B, T*D] feature-concatenated: out[b, t*D + d]
        float4* __restrict__ o =
            (float4*)(out + ((long long)b * T_TABLES + t) * EMB_D);
        o[lane] = acc;

        bag = next_bag;
    }
}

extern "C" void kernel_launch(void* const* d_in, const int* in_sizes, int n_in,
                              void* d_out, int out_size)
{
    const int*   indices = (const int*)d_in[0];
    const int*   offsets = (const int*)d_in[1];
    const float* weights = (const float*)d_in[2];
    float*       out     = (float*)d_out;

    emb_bag_kernel<<<CTAS, THREADS>>>(indices, offsets, weights, out);
}

// round 6
// speedup vs baseline: 1.0218x; 1.0218x over previous
#include <cuda_runtime.h>
#include <cuda_bf16.h>
#include <cstdint>

// Problem constants (match reference setup_inputs)
#define T_TABLES 8
#define N_ROWS   100000
#define EMB_D    128
#define N_BAGS_B 8192

#define CTAS_PER_SM 3
#define NUM_SMS     148
#define CTAS        (NUM_SMS * CTAS_PER_SM)   // 444
#define THREADS     256                       // 8 warps per CTA

// Persistent kernel: each warp grid-strides over bags.
// Lane l owns floats [4l, 4l+4) of the D=128 row.
__global__ __launch_bounds__(THREADS, CTAS_PER_SM) void emb_bag_kernel(
    const int* __restrict__ indices,
    const int* __restrict__ offsets,
    const float* __restrict__ weights,
    float* __restrict__ out)
{
    const int lane        = threadIdx.x & 31;
    const int warp0       = (blockIdx.x * THREADS + threadIdx.x) >> 5;
    const int total_warps = (CTAS * THREADS) >> 5;
    const int num_bags    = T_TABLES * N_BAGS_B;

    const char* __restrict__ wbytes =
        (const char*)weights + (unsigned)lane * 16u;

    int bag = warp0;
    if (bag >= num_bags) return;

    // Prefetch state for the first bag handled by this warp.
    int pf_start = offsets[bag];
    int pf_end   = offsets[bag + 1];
    int pf_idx   = (lane < pf_end - pf_start) ? indices[pf_start + lane] : 0;

    while (bag < num_bags) {
        const int t     = bag / N_BAGS_B;
        const int b     = bag - t * N_BAGS_B;
        const int start = pf_start;
        const int end   = pf_end;
        int       myidx = pf_idx;

        // Issue next bag's index/offset loads early so their latency hides
        // under this bag's gather burst.
        const int next_bag = bag + total_warps;
        if (next_bag < num_bags) {
            pf_start = offsets[next_bag];
            pf_end   = offsets[next_bag + 1];
            pf_idx   = (lane < pf_end - pf_start) ? indices[pf_start + lane] : 0;
        }

        // Table base: 64-bit once per bag; per-row offset is 32-bit (<51.2MB).
        const char* __restrict__ wbase =
            wbytes + (long long)t * (N_ROWS * EMB_D * 4ll);

        float4 acc = make_float4(0.f, 0.f, 0.f, 0.f);

        const int n0 = end - start;
        if (n0 == 32) {
            // Deep-MLP path: with the 85-reg budget ptxas can front-batch
            // ~20 independent LDG.128s. Two independent accumulator pairs
            // shorten the FADD dependence chain and decouple load groups.
            float4 acc2 = make_float4(0.f, 0.f, 0.f, 0.f);
            #pragma unroll
            for (int j = 0; j < 32; j += 2) {
                const unsigned r0 = (unsigned)__shfl_sync(0xffffffffu, myidx, j);
                const unsigned r1 = (unsigned)__shfl_sync(0xffffffffu, myidx, j + 1);
                const float4 v0 = __ldcg((const float4*)(wbase + (r0 << 9)));
                const float4 v1 = __ldcg((const float4*)(wbase + (r1 << 9)));
                acc.x  += v0.x; acc.y  += v0.y; acc.z  += v0.z; acc.w  += v0.w;
                acc2.x += v1.x; acc2.y += v1.y; acc2.z += v1.z; acc2.w += v1.w;
            }
            acc.x += acc2.x; acc.y += acc2.y; acc.z += acc2.z; acc.w += acc2.w;
        } else {
            // Generic path: bags longer/shorter than 32.
            int i = start;
            int cur = myidx;
            int n = min(32, end - i);
            while (n > 0) {
                for (int j = 0; j < n; ++j) {
                    const unsigned r = (unsigned)__shfl_sync(0xffffffffu, cur, j);
                    const float4 v = __ldcg((const float4*)(wbase + (r << 9)));
                    acc.x += v.x; acc.y += v.y; acc.z += v.z; acc.w += v.w;
                }
                i += n;
                n = min(32, end - i);
                if (n > 0) cur = (lane < n) ? indices[i + lane] : 0;
            }
        }

        // Output layout: [B, T*D] feature-concatenated: out[b, t*D + d]
        float4* __restrict__ o =
            (float4*)(out + ((long long)b * T_TABLES + t) * EMB_D);
        o[lane] = acc;

        bag = next_bag;
    }
}

extern "C" void kernel_launch(void* const* d_in, const int* in_sizes, int n_in,
                              void* d_out, int out_size)
{
    const int*   indices = (const int*)d_in[0];
    const int*   offsets = (const int*)d_in[1];
    const float* weights = (const float*)d_in[2];
    float*       out     = (float*)d_out;

    emb_bag_kernel<<<CTAS, THREADS>>>(indices, offsets, weights, out);
}